// round 1
// baseline (speedup 1.0000x reference)
#include <cuda_runtime.h>
#include <cuda_bf16.h>

// Problem constants
#define B_    128
#define T_    256
#define D_    384
#define H_    6
#define HD_   64
#define L_    6
#define FF_   1536
#define V_    95
#define NTOK  (B_ * T_)   // 32768

// ---------------------------------------------------------------------------
// Scratch (device globals: the sanctioned alloc-free scratch mechanism)
// ---------------------------------------------------------------------------
__device__ float g_x  [NTOK * D_];   // residual stream
__device__ float g_h  [NTOK * D_];   // layernorm out / attention out (reused)
__device__ float g_q  [NTOK * D_];
__device__ float g_k  [NTOK * D_];
__device__ float g_v  [NTOK * D_];
__device__ float g_ffn[NTOK * FF_];

// ---------------------------------------------------------------------------
// Embedding: x[b,t,:] = tok_emb[idx[b,t],:] + pos_emb[t,:]
// ---------------------------------------------------------------------------
__global__ void embed_kernel(const int* __restrict__ idx,
                             const float* __restrict__ tok,
                             const float* __restrict__ pos,
                             float* __restrict__ x)
{
    int i = blockIdx.x * blockDim.x + threadIdx.x;   // over NTOK*D_
    if (i >= NTOK * D_) return;
    int d   = i % D_;
    int row = i / D_;
    int t   = row % T_;
    int tk  = idx[row];
    x[i] = tok[tk * D_ + d] + pos[t * D_ + d];
}

// ---------------------------------------------------------------------------
// LayerNorm: one block (128 threads) per token row of 384
// ---------------------------------------------------------------------------
__global__ void __launch_bounds__(128)
layernorm_kernel(const float* __restrict__ x,
                 const float* __restrict__ gam,
                 const float* __restrict__ beta,
                 float* __restrict__ out)
{
    int row = blockIdx.x;
    int tid = threadIdx.x;
    const float* xr = x + (size_t)row * D_;

    float v0 = xr[tid];
    float v1 = xr[tid + 128];
    float v2 = xr[tid + 256];

    float s  = v0 + v1 + v2;
    float sq = v0 * v0 + v1 * v1 + v2 * v2;

    #pragma unroll
    for (int off = 16; off > 0; off >>= 1) {
        s  += __shfl_xor_sync(0xffffffffu, s,  off);
        sq += __shfl_xor_sync(0xffffffffu, sq, off);
    }
    __shared__ float ss[4], ssq[4];
    int w = tid >> 5;
    if ((tid & 31) == 0) { ss[w] = s; ssq[w] = sq; }
    __syncthreads();
    s  = ss[0]  + ss[1]  + ss[2]  + ss[3];
    sq = ssq[0] + ssq[1] + ssq[2] + ssq[3];

    const float invn = 1.0f / (float)D_;
    float mean = s * invn;
    float var  = sq * invn - mean * mean;
    float inv  = rsqrtf(var + 1e-5f);

    float* orow = out + (size_t)row * D_;
    orow[tid]       = (v0 - mean) * inv * gam[tid]       + beta[tid];
    orow[tid + 128] = (v1 - mean) * inv * gam[tid + 128] + beta[tid + 128];
    orow[tid + 256] = (v2 - mean) * inv * gam[tid + 256] + beta[tid + 256];
}

// ---------------------------------------------------------------------------
// SGEMM: C[M,N] (+)= A[M,K] @ B[K,N] (+ bias) (relu)
// 128x128 block tile, BK=8, 8x8 thread tile, 256 threads.
// Requires M%128==0, N%128==0, K%8==0 (true for all in-model GEMMs).
// ---------------------------------------------------------------------------
#define BM 128
#define BN 128
#define BK 8
#define TM 8
#define TN 8

template<bool BIAS, bool RELU, bool RESID>
__global__ void __launch_bounds__(256)
sgemm_kernel(int M, int N, int K,
             const float* __restrict__ A,
             const float* __restrict__ B,
             const float* __restrict__ bias,
             float* __restrict__ C)
{
    __shared__ float As[BK][BM];
    __shared__ float Bs[BK][BN];

    const int bx  = blockIdx.x;   // N tile
    const int by  = blockIdx.y;   // M tile
    const int tid = threadIdx.x;

    const int tcol = tid % (BN / TN);  // 0..15
    const int trow = tid / (BN / TN);  // 0..15

    // A load mapping: 128x8 tile = 256 float4s
    const int aRow = tid >> 1;            // 0..127
    const int aCol = (tid & 1) * 4;       // 0 or 4
    // B load mapping: 8x128 tile = 256 float4s
    const int bRow = tid >> 5;            // 0..7
    const int bCol = (tid & 31) * 4;      // 0..124

    const float* Aptr = A + (size_t)by * BM * K;
    const float* Bptr = B + (size_t)bx * BN;
    float*       Cptr = C + (size_t)by * BM * N + (size_t)bx * BN;

    float acc[TM][TN];
    #pragma unroll
    for (int i = 0; i < TM; i++)
        #pragma unroll
        for (int j = 0; j < TN; j++)
            acc[i][j] = 0.0f;

    float regM[TM], regN[TN];

    for (int k0 = 0; k0 < K; k0 += BK) {
        float4 a4 = *reinterpret_cast<const float4*>(Aptr + (size_t)aRow * K + k0 + aCol);
        As[aCol + 0][aRow] = a4.x;
        As[aCol + 1][aRow] = a4.y;
        As[aCol + 2][aRow] = a4.z;
        As[aCol + 3][aRow] = a4.w;
        *reinterpret_cast<float4*>(&Bs[bRow][bCol]) =
            *reinterpret_cast<const float4*>(Bptr + (size_t)(k0 + bRow) * N + bCol);
        __syncthreads();

        #pragma unroll
        for (int k = 0; k < BK; k++) {
            #pragma unroll
            for (int i = 0; i < TM; i++) regM[i] = As[k][trow * TM + i];
            #pragma unroll
            for (int j = 0; j < TN; j++) regN[j] = Bs[k][tcol * TN + j];
            #pragma unroll
            for (int i = 0; i < TM; i++)
                #pragma unroll
                for (int j = 0; j < TN; j++)
                    acc[i][j] = fmaf(regM[i], regN[j], acc[i][j]);
        }
        __syncthreads();
    }

    #pragma unroll
    for (int i = 0; i < TM; i++) {
        int row = trow * TM + i;
        #pragma unroll
        for (int j = 0; j < TN; j += 4) {
            int col = tcol * TN + j;
            float4 v = make_float4(acc[i][j], acc[i][j+1], acc[i][j+2], acc[i][j+3]);
            float* cp = Cptr + (size_t)row * N + col;
            if (BIAS) {
                const float* bp = bias + (size_t)bx * BN + col;
                v.x += bp[0]; v.y += bp[1]; v.z += bp[2]; v.w += bp[3];
            }
            if (RELU) {
                v.x = fmaxf(v.x, 0.0f); v.y = fmaxf(v.y, 0.0f);
                v.z = fmaxf(v.z, 0.0f); v.w = fmaxf(v.w, 0.0f);
            }
            if (RESID) {
                float4 old = *reinterpret_cast<const float4*>(cp);
                v.x += old.x; v.y += old.y; v.z += old.z; v.w += old.w;
            }
            *reinterpret_cast<float4*>(cp) = v;
        }
    }
}

// ---------------------------------------------------------------------------
// Causal attention: one CTA per (b,h). K,V tiles in dynamic smem (128 KB).
// Thread i = query row i, online softmax over keys j<=i.
// ---------------------------------------------------------------------------
__global__ void __launch_bounds__(256)
attn_kernel(const float* __restrict__ q,
            const float* __restrict__ k,
            const float* __restrict__ v,
            float* __restrict__ out)
{
    extern __shared__ float smem[];
    float* ks = smem;              // [T_][HD_]
    float* vs = smem + T_ * HD_;   // [T_][HD_]

    int bh = blockIdx.x;
    int b  = bh / H_;
    int h  = bh % H_;
    int tid = threadIdx.x;

    const size_t base = (size_t)(b * T_) * D_ + h * HD_;

    // cooperative load: thread tid loads row tid of K and V (64 floats each)
    const float4* krow = reinterpret_cast<const float4*>(k + base + (size_t)tid * D_);
    const float4* vrow = reinterpret_cast<const float4*>(v + base + (size_t)tid * D_);
    float4* ksd = reinterpret_cast<float4*>(ks + tid * HD_);
    float4* vsd = reinterpret_cast<float4*>(vs + tid * HD_);
    #pragma unroll
    for (int d4 = 0; d4 < HD_ / 4; d4++) {
        ksd[d4] = krow[d4];
        vsd[d4] = vrow[d4];
    }
    __syncthreads();

    float qr[HD_];
    const float4* qrow = reinterpret_cast<const float4*>(q + base + (size_t)tid * D_);
    #pragma unroll
    for (int d4 = 0; d4 < HD_ / 4; d4++) {
        float4 t = qrow[d4];
        qr[d4 * 4 + 0] = t.x; qr[d4 * 4 + 1] = t.y;
        qr[d4 * 4 + 2] = t.z; qr[d4 * 4 + 3] = t.w;
    }

    float m = -1e30f, l = 0.0f;
    float o[HD_];
    #pragma unroll
    for (int d = 0; d < HD_; d++) o[d] = 0.0f;

    const float scale = 0.125f;  // 64^-0.5

    for (int j = 0; j <= tid; j++) {
        const float* kj = ks + j * HD_;
        float s = 0.0f;
        #pragma unroll
        for (int d = 0; d < HD_; d++) s = fmaf(qr[d], kj[d], s);
        s *= scale;

        if (s > m) {
            float corr = __expf(m - s);   // 0 on first iteration (m=-1e30)
            l *= corr;
            #pragma unroll
            for (int d = 0; d < HD_; d++) o[d] *= corr;
            m = s;
        }
        float p = __expf(s - m);
        l += p;
        const float* vj = vs + j * HD_;
        #pragma unroll
        for (int d = 0; d < HD_; d++) o[d] = fmaf(p, vj[d], o[d]);
    }

    float invl = 1.0f / l;
    float* op = out + base + (size_t)tid * D_;
    #pragma unroll
    for (int d = 0; d < HD_; d++) op[d] = o[d] * invl;
}

// ---------------------------------------------------------------------------
// Head: out[row, n] = h[row,:] @ W[:,n] + b[n], N=95 (odd size -> own kernel)
// One block per token row; A row staged in smem; W stays L2-resident (146 KB).
// ---------------------------------------------------------------------------
__global__ void __launch_bounds__(128)
head_kernel(const float* __restrict__ h,
            const float* __restrict__ W,
            const float* __restrict__ bias,
            float* __restrict__ out)
{
    __shared__ float a[D_];
    int row = blockIdx.x;
    for (int i = threadIdx.x; i < D_; i += 128)
        a[i] = h[(size_t)row * D_ + i];
    __syncthreads();

    int n = threadIdx.x;
    if (n < V_) {
        float acc = bias[n];
        #pragma unroll 4
        for (int kk = 0; kk < D_; kk++)
            acc = fmaf(a[kk], W[(size_t)kk * V_ + n], acc);
        out[(size_t)row * V_ + n] = acc;
    }
}

// ---------------------------------------------------------------------------
// Host launcher
// ---------------------------------------------------------------------------
static void launch_gemm(int M, int N, int K,
                        const float* A, const float* Bm, const float* bias,
                        float* C, int mode /*0=plain,1=bias+relu,2=bias+resid*/)
{
    dim3 grid(N / BN, M / BM);
    if (mode == 0)      sgemm_kernel<false, false, false><<<grid, 256>>>(M, N, K, A, Bm, bias, C);
    else if (mode == 1) sgemm_kernel<true,  true,  false><<<grid, 256>>>(M, N, K, A, Bm, bias, C);
    else                sgemm_kernel<true,  false, true ><<<grid, 256>>>(M, N, K, A, Bm, bias, C);
}

extern "C" void kernel_launch(void* const* d_in, const int* in_sizes, int n_in,
                              void* d_out, int out_size)
{
    const int*   idx    = (const int*)  d_in[0];
    const float* tok    = (const float*)d_in[1];
    const float* pos    = (const float*)d_in[2];
    const float* ln1_s  = (const float*)d_in[3];
    const float* ln1_b  = (const float*)d_in[4];
    const float* wq     = (const float*)d_in[5];
    const float* wk     = (const float*)d_in[6];
    const float* wv     = (const float*)d_in[7];
    const float* wo     = (const float*)d_in[8];
    const float* bo     = (const float*)d_in[9];
    const float* ln2_s  = (const float*)d_in[10];
    const float* ln2_b  = (const float*)d_in[11];
    const float* w1     = (const float*)d_in[12];
    const float* b1     = (const float*)d_in[13];
    const float* w2     = (const float*)d_in[14];
    const float* b2     = (const float*)d_in[15];
    const float* lnf_s  = (const float*)d_in[16];
    const float* lnf_b  = (const float*)d_in[17];
    const float* head_w = (const float*)d_in[18];
    const float* head_b = (const float*)d_in[19];
    float* out = (float*)d_out;

    float *x, *h, *q, *k, *v, *ffn;
    cudaGetSymbolAddress((void**)&x,   g_x);
    cudaGetSymbolAddress((void**)&h,   g_h);
    cudaGetSymbolAddress((void**)&q,   g_q);
    cudaGetSymbolAddress((void**)&k,   g_k);
    cudaGetSymbolAddress((void**)&v,   g_v);
    cudaGetSymbolAddress((void**)&ffn, g_ffn);

    cudaFuncSetAttribute(attn_kernel,
                         cudaFuncAttributeMaxDynamicSharedMemorySize,
                         2 * T_ * HD_ * (int)sizeof(float));

    // Embedding
    {
        int total = NTOK * D_;
        embed_kernel<<<(total + 255) / 256, 256>>>(idx, tok, pos, x);
    }

    for (int l = 0; l < L_; l++) {
        const float* Wq = wq + (size_t)l * D_ * D_;
        const float* Wk = wk + (size_t)l * D_ * D_;
        const float* Wv = wv + (size_t)l * D_ * D_;
        const float* Wo = wo + (size_t)l * D_ * D_;
        const float* Bo = bo + (size_t)l * D_;
        const float* W1 = w1 + (size_t)l * D_ * FF_;
        const float* B1 = b1 + (size_t)l * FF_;
        const float* W2 = w2 + (size_t)l * FF_ * D_;
        const float* B2 = b2 + (size_t)l * D_;

        // ln1
        layernorm_kernel<<<NTOK, 128>>>(x, ln1_s + (size_t)l * D_, ln1_b + (size_t)l * D_, h);
        // qkv
        launch_gemm(NTOK, D_, D_, h, Wq, nullptr, q, 0);
        launch_gemm(NTOK, D_, D_, h, Wk, nullptr, k, 0);
        launch_gemm(NTOK, D_, D_, h, Wv, nullptr, v, 0);
        // attention (writes into h — ln1 output is consumed by this point)
        attn_kernel<<<B_ * H_, 256, 2 * T_ * HD_ * (int)sizeof(float)>>>(q, k, v, h);
        // x += attn @ Wo + Bo
        launch_gemm(NTOK, D_, D_, h, Wo, Bo, x, 2);
        // ln2
        layernorm_kernel<<<NTOK, 128>>>(x, ln2_s + (size_t)l * D_, ln2_b + (size_t)l * D_, h);
        // ffn = relu(h @ W1 + B1)
        launch_gemm(NTOK, FF_, D_, h, W1, B1, ffn, 1);
        // x += ffn @ W2 + B2
        launch_gemm(NTOK, D_, FF_, ffn, W2, B2, x, 2);
    }

    // Final layernorm + head
    layernorm_kernel<<<NTOK, 128>>>(x, lnf_s, lnf_b, h);
    head_kernel<<<NTOK, 128>>>(h, head_w, head_b, out);
}

// round 4
// speedup vs baseline: 1.7751x; 1.7751x over previous
#include <cuda_runtime.h>
#include <cuda_bf16.h>
#include <cstdint>

// Problem constants
#define B_    128
#define T_    256
#define D_    384
#define H_    6
#define HD_   64
#define L_    6
#define FF_   1536
#define V_    95
#define NTOK  (B_ * T_)   // 32768

// Single dynamic-smem symbol for the whole TU
extern __shared__ char dyn_smem[];

// ---------------------------------------------------------------------------
// Baseline-PTX helpers (compute_103-safe: cp.async + mma.sync only)
// ---------------------------------------------------------------------------
__device__ __forceinline__ uint32_t smem_u32(const void* p) {
    uint32_t a;
    asm("{ .reg .u64 t; cvta.to.shared.u64 t, %1; cvt.u32.u64 %0, t; }"
        : "=r"(a) : "l"(p));
    return a;
}

__device__ __forceinline__ void cp16(uint32_t dst, const void* src) {
    asm volatile("cp.async.cg.shared.global [%0], [%1], 16;"
                 :: "r"(dst), "l"(src));
}
#define CP_COMMIT() asm volatile("cp.async.commit_group;" ::: "memory")
#define CP_WAIT0()  asm volatile("cp.async.wait_group 0;" ::: "memory")
#define CP_WAIT1()  asm volatile("cp.async.wait_group 1;" ::: "memory")

// m16n8k16 bf16 MMA, fp32 accumulate (sm_80 baseline PTX)
__device__ __forceinline__ void mma16816(float* c, const uint32_t* a,
                                         const uint32_t* b) {
    asm volatile(
        "mma.sync.aligned.m16n8k16.row.col.f32.bf16.bf16.f32 "
        "{%0,%1,%2,%3},{%4,%5,%6,%7},{%8,%9},{%0,%1,%2,%3};"
        : "+f"(c[0]), "+f"(c[1]), "+f"(c[2]), "+f"(c[3])
        : "r"(a[0]), "r"(a[1]), "r"(a[2]), "r"(a[3]),
          "r"(b[0]), "r"(b[1]));
}

// ---------------------------------------------------------------------------
// Scratch (device globals)
// ---------------------------------------------------------------------------
#define WTOT (L_ * (4 * D_ * D_ + 2 * D_ * FF_))
#define OFF_WQ 0
#define OFF_WK (L_ * D_ * D_)
#define OFF_WV (2 * L_ * D_ * D_)
#define OFF_WO (3 * L_ * D_ * D_)
#define OFF_W1 (4 * L_ * D_ * D_)
#define OFF_W2 (4 * L_ * D_ * D_ + L_ * D_ * FF_)

__device__ float g_x  [NTOK * D_];
__device__ float g_h  [NTOK * D_];
__device__ float g_q  [NTOK * D_];
__device__ float g_k  [NTOK * D_];
__device__ float g_v  [NTOK * D_];
__device__ float g_ffn[NTOK * FF_];
__device__ __nv_bfloat16 g_ah[NTOK * FF_];
__device__ __nv_bfloat16 g_al[NTOK * FF_];
__device__ __nv_bfloat16 g_wh[WTOT];
__device__ __nv_bfloat16 g_wl[WTOT];

// ---------------------------------------------------------------------------
// Embedding
// ---------------------------------------------------------------------------
__global__ void embed_kernel(const int* __restrict__ idx,
                             const float* __restrict__ tok,
                             const float* __restrict__ pos,
                             float* __restrict__ x)
{
    int i = blockIdx.x * blockDim.x + threadIdx.x;
    if (i >= NTOK * D_) return;
    int d   = i % D_;
    int row = i / D_;
    int t   = row % T_;
    int tk  = idx[row];
    x[i] = tok[tk * D_ + d] + pos[t * D_ + d];
}

// ---------------------------------------------------------------------------
// LayerNorm (one 128-thread block per token)
// ---------------------------------------------------------------------------
__global__ void __launch_bounds__(128)
layernorm_kernel(const float* __restrict__ x,
                 const float* __restrict__ gam,
                 const float* __restrict__ beta,
                 float* __restrict__ out)
{
    int row = blockIdx.x;
    int tid = threadIdx.x;
    const float* xr = x + (size_t)row * D_;

    float v0 = xr[tid];
    float v1 = xr[tid + 128];
    float v2 = xr[tid + 256];

    float s  = v0 + v1 + v2;
    float sq = v0 * v0 + v1 * v1 + v2 * v2;

    #pragma unroll
    for (int off = 16; off > 0; off >>= 1) {
        s  += __shfl_xor_sync(0xffffffffu, s,  off);
        sq += __shfl_xor_sync(0xffffffffu, sq, off);
    }
    __shared__ float ss[4], ssq[4];
    int w = tid >> 5;
    if ((tid & 31) == 0) { ss[w] = s; ssq[w] = sq; }
    __syncthreads();
    s  = ss[0]  + ss[1]  + ss[2]  + ss[3];
    sq = ssq[0] + ssq[1] + ssq[2] + ssq[3];

    const float invn = 1.0f / (float)D_;
    float mean = s * invn;
    float var  = sq * invn - mean * mean;
    float inv  = rsqrtf(var + 1e-5f);

    float* orow = out + (size_t)row * D_;
    orow[tid]       = (v0 - mean) * inv * gam[tid]       + beta[tid];
    orow[tid + 128] = (v1 - mean) * inv * gam[tid + 128] + beta[tid + 128];
    orow[tid + 256] = (v2 - mean) * inv * gam[tid + 256] + beta[tid + 256];
}

// ---------------------------------------------------------------------------
// Split fp32 -> (hi, lo) bf16, vectorized x4
// ---------------------------------------------------------------------------
__global__ void split4_kernel(const float* __restrict__ x,
                              __nv_bfloat16* __restrict__ hi,
                              __nv_bfloat16* __restrict__ lo, int n4)
{
    int i = blockIdx.x * blockDim.x + threadIdx.x;
    if (i >= n4) return;
    float4 v = reinterpret_cast<const float4*>(x)[i];
    __nv_bfloat16 h0 = __float2bfloat16(v.x);
    __nv_bfloat16 h1 = __float2bfloat16(v.y);
    __nv_bfloat16 h2 = __float2bfloat16(v.z);
    __nv_bfloat16 h3 = __float2bfloat16(v.w);
    __nv_bfloat16 l0 = __float2bfloat16(v.x - __bfloat162float(h0));
    __nv_bfloat16 l1 = __float2bfloat16(v.y - __bfloat162float(h1));
    __nv_bfloat16 l2 = __float2bfloat16(v.z - __bfloat162float(h2));
    __nv_bfloat16 l3 = __float2bfloat16(v.w - __bfloat162float(h3));
    __nv_bfloat162* hp = reinterpret_cast<__nv_bfloat162*>(hi);
    __nv_bfloat162* lp = reinterpret_cast<__nv_bfloat162*>(lo);
    hp[2 * i]     = __nv_bfloat162{h0, h1};
    hp[2 * i + 1] = __nv_bfloat162{h2, h3};
    lp[2 * i]     = __nv_bfloat162{l0, l1};
    lp[2 * i + 1] = __nv_bfloat162{l2, l3};
}

// ---------------------------------------------------------------------------
// Transpose + split: W[z][Kd][Nd] fp32 -> out[z][Nd][Kd] (hi,lo) bf16
// ---------------------------------------------------------------------------
__global__ void tsplit_kernel(const float* __restrict__ W,
                              __nv_bfloat16* __restrict__ oh,
                              __nv_bfloat16* __restrict__ ol,
                              int Kd, int Nd)
{
    __shared__ float t[32][33];
    size_t zoff = (size_t)blockIdx.z * Kd * Nd;
    int n0 = blockIdx.x * 32, k0 = blockIdx.y * 32;
    const float* Wz = W + zoff;
    for (int r = threadIdx.y; r < 32; r += 8)
        t[r][threadIdx.x] = Wz[(size_t)(k0 + r) * Nd + n0 + threadIdx.x];
    __syncthreads();
    __nv_bfloat16* ohz = oh + zoff;
    __nv_bfloat16* olz = ol + zoff;
    for (int r = threadIdx.y; r < 32; r += 8) {
        float v = t[threadIdx.x][r];   // = W[k0+tx][n0+r]
        __nv_bfloat16 h = __float2bfloat16(v);
        __nv_bfloat16 l = __float2bfloat16(v - __bfloat162float(h));
        ohz[(size_t)(n0 + r) * Kd + k0 + threadIdx.x] = h;
        olz[(size_t)(n0 + r) * Kd + k0 + threadIdx.x] = l;
    }
}

// ---------------------------------------------------------------------------
// mma.sync GEMM: C[M,N] (+)= A[M,K] @ Bt[N,K]^T with bf16x3 precision split.
// 128x128 CTA tile, BK=32, 256 threads (8 warps, 4x2), warp tile 32x64.
// cp.async double-buffered: 4 tiles (Ah, Al, Bh, Bl) per stage.
// smem row stride = 40 bf16 (80B): 16B-aligned rows, bank period 8.
// ---------------------------------------------------------------------------
#define BKG        32
#define ROW_BF16   40                    // bf16 elements per smem row
#define ROW_BYTES  80
#define ROW_WORDS  20                    // 32-bit words per row
#define TILE_B     (128 * ROW_BYTES)     // 10240 bytes
#define STAGE_B    (4 * TILE_B)          // 40960 bytes
#define GEMM_SMEM  (2 * STAGE_B)         // 81920 bytes

template<bool BIAS, bool RELU, bool RESID>
__global__ void __launch_bounds__(256, 1)
mma_gemm(int M, int N, int K,
         const __nv_bfloat16* __restrict__ Ah,
         const __nv_bfloat16* __restrict__ Al,
         const __nv_bfloat16* __restrict__ Bh,   // [N,K]
         const __nv_bfloat16* __restrict__ Bl,   // [N,K]
         const float* __restrict__ bias,
         float* __restrict__ C)
{
    char* smem = dyn_smem;
    const uint32_t sb = smem_u32(smem);

    const int tid  = threadIdx.x;
    const int wid  = tid >> 5;
    const int lane = tid & 31;
    const int wm   = wid & 3;    // 0..3 -> M offset 32*wm
    const int wn   = wid >> 2;   // 0..1 -> N offset 64*wn
    const int g    = lane >> 2;  // group 0..7
    const int t    = lane & 3;   // thread-in-group

    const int n0 = blockIdx.x * 128;
    const int m0 = blockIdx.y * 128;

    const __nv_bfloat16* gsrc[4] = {
        Ah + (size_t)m0 * K, Al + (size_t)m0 * K,
        Bh + (size_t)n0 * K, Bl + (size_t)n0 * K };

    const int KT = K / BKG;

    // ---- stage loader: 4 tiles x 128 rows x 32 bf16 (4 x 16B chunks/row) ----
    auto load_stage = [&](int kt, int s) {
        const uint32_t sdst = sb + s * STAGE_B;
        const int kc = kt * BKG;
        #pragma unroll
        for (int tile = 0; tile < 4; tile++) {
            const __nv_bfloat16* gp = gsrc[tile];
            #pragma unroll
            for (int i = 0; i < 2; i++) {
                int idx = i * 256 + tid;
                int row = idx >> 2, ch = idx & 3;
                cp16(sdst + tile * TILE_B + row * ROW_BYTES + ch * 16,
                     gp + (size_t)row * K + kc + ch * 8);
            }
        }
    };

    float acc[2][8][4];
    #pragma unroll
    for (int i = 0; i < 2; i++)
        #pragma unroll
        for (int j = 0; j < 8; j++)
            #pragma unroll
            for (int c = 0; c < 4; c++) acc[i][j][c] = 0.0f;

    load_stage(0, 0);
    CP_COMMIT();

    for (int kt = 0; kt < KT; kt++) {
        const int s = kt & 1;
        if (kt + 1 < KT) {
            load_stage(kt + 1, s ^ 1);
            CP_COMMIT();
            CP_WAIT1();
        } else {
            CP_WAIT0();
        }
        __syncthreads();

        const uint32_t* Awh = reinterpret_cast<const uint32_t*>(smem + s * STAGE_B);
        const uint32_t* Awl = reinterpret_cast<const uint32_t*>(smem + s * STAGE_B + TILE_B);
        const uint32_t* Bwh = reinterpret_cast<const uint32_t*>(smem + s * STAGE_B + 2 * TILE_B);
        const uint32_t* Bwl = reinterpret_cast<const uint32_t*>(smem + s * STAGE_B + 3 * TILE_B);

        #pragma unroll
        for (int ks = 0; ks < 2; ks++) {
            const int kw = ks * 8 + t;   // word offset of k = ks*16 + 2t

            uint32_t ah[2][4], al[2][4];
            #pragma unroll
            for (int i = 0; i < 2; i++) {
                int r0 = (wm * 32 + i * 16 + g) * ROW_WORDS;
                ah[i][0] = Awh[r0 + kw];
                ah[i][1] = Awh[r0 + 8 * ROW_WORDS + kw];
                ah[i][2] = Awh[r0 + kw + 4];
                ah[i][3] = Awh[r0 + 8 * ROW_WORDS + kw + 4];
                al[i][0] = Awl[r0 + kw];
                al[i][1] = Awl[r0 + 8 * ROW_WORDS + kw];
                al[i][2] = Awl[r0 + kw + 4];
                al[i][3] = Awl[r0 + 8 * ROW_WORDS + kw + 4];
            }
            uint32_t bh[8][2], bl[8][2];
            #pragma unroll
            for (int j = 0; j < 8; j++) {
                int rn = (wn * 64 + j * 8 + g) * ROW_WORDS;
                bh[j][0] = Bwh[rn + kw];
                bh[j][1] = Bwh[rn + kw + 4];
                bl[j][0] = Bwl[rn + kw];
                bl[j][1] = Bwl[rn + kw + 4];
            }
            #pragma unroll
            for (int i = 0; i < 2; i++)
                #pragma unroll
                for (int j = 0; j < 8; j++) {
                    mma16816(acc[i][j], ah[i], bh[j]);
                    mma16816(acc[i][j], ah[i], bl[j]);
                    mma16816(acc[i][j], al[i], bh[j]);
                }
        }
        __syncthreads();
    }

    // ---- epilogue ----
    #pragma unroll
    for (int i = 0; i < 2; i++) {
        const int rm = m0 + wm * 32 + i * 16 + g;
        #pragma unroll
        for (int j = 0; j < 8; j++) {
            const int cn = n0 + wn * 64 + j * 8 + 2 * t;
            float2 v0 = make_float2(acc[i][j][0], acc[i][j][1]);
            float2 v1 = make_float2(acc[i][j][2], acc[i][j][3]);
            if (BIAS) {
                float b0 = bias[cn], b1 = bias[cn + 1];
                v0.x += b0; v0.y += b1;
                v1.x += b0; v1.y += b1;
            }
            if (RELU) {
                v0.x = fmaxf(v0.x, 0.f); v0.y = fmaxf(v0.y, 0.f);
                v1.x = fmaxf(v1.x, 0.f); v1.y = fmaxf(v1.y, 0.f);
            }
            float* p0 = C + (size_t)rm * N + cn;
            float* p1 = C + (size_t)(rm + 8) * N + cn;
            if (RESID) {
                float2 o0 = *reinterpret_cast<const float2*>(p0);
                float2 o1 = *reinterpret_cast<const float2*>(p1);
                v0.x += o0.x; v0.y += o0.y;
                v1.x += o1.x; v1.y += o1.y;
            }
            *reinterpret_cast<float2*>(p0) = v0;
            *reinterpret_cast<float2*>(p1) = v1;
        }
    }
}

// ---------------------------------------------------------------------------
// Causal attention: one CTA per (b,h); K,V tiles in dynamic smem (128 KB).
// ---------------------------------------------------------------------------
__global__ void __launch_bounds__(256)
attn_kernel(const float* __restrict__ q,
            const float* __restrict__ k,
            const float* __restrict__ v,
            float* __restrict__ out)
{
    float* smem = reinterpret_cast<float*>(dyn_smem);
    float* ks = smem;
    float* vs = smem + T_ * HD_;

    int bh = blockIdx.x;
    int b  = bh / H_;
    int h  = bh % H_;
    int tid = threadIdx.x;

    const size_t base = (size_t)(b * T_) * D_ + h * HD_;

    const float4* krow = reinterpret_cast<const float4*>(k + base + (size_t)tid * D_);
    const float4* vrow = reinterpret_cast<const float4*>(v + base + (size_t)tid * D_);
    float4* ksd = reinterpret_cast<float4*>(ks + tid * HD_);
    float4* vsd = reinterpret_cast<float4*>(vs + tid * HD_);
    #pragma unroll
    for (int d4 = 0; d4 < HD_ / 4; d4++) {
        ksd[d4] = krow[d4];
        vsd[d4] = vrow[d4];
    }
    __syncthreads();

    float qr[HD_];
    const float4* qrow = reinterpret_cast<const float4*>(q + base + (size_t)tid * D_);
    #pragma unroll
    for (int d4 = 0; d4 < HD_ / 4; d4++) {
        float4 t = qrow[d4];
        qr[d4 * 4 + 0] = t.x; qr[d4 * 4 + 1] = t.y;
        qr[d4 * 4 + 2] = t.z; qr[d4 * 4 + 3] = t.w;
    }

    float m = -1e30f, l = 0.0f;
    float o[HD_];
    #pragma unroll
    for (int d = 0; d < HD_; d++) o[d] = 0.0f;

    const float scale = 0.125f;

    for (int j = 0; j <= tid; j++) {
        const float* kj = ks + j * HD_;
        float s = 0.0f;
        #pragma unroll
        for (int d = 0; d < HD_; d++) s = fmaf(qr[d], kj[d], s);
        s *= scale;

        if (s > m) {
            float corr = __expf(m - s);
            l *= corr;
            #pragma unroll
            for (int d = 0; d < HD_; d++) o[d] *= corr;
            m = s;
        }
        float p = __expf(s - m);
        l += p;
        const float* vj = vs + j * HD_;
        #pragma unroll
        for (int d = 0; d < HD_; d++) o[d] = fmaf(p, vj[d], o[d]);
    }

    float invl = 1.0f / l;
    float* op = out + base + (size_t)tid * D_;
    #pragma unroll
    for (int d = 0; d < HD_; d++) op[d] = o[d] * invl;
}

// ---------------------------------------------------------------------------
// Head GEMM (N=95, fp32)
// ---------------------------------------------------------------------------
__global__ void __launch_bounds__(128)
head_kernel(const float* __restrict__ h,
            const float* __restrict__ W,
            const float* __restrict__ bias,
            float* __restrict__ out)
{
    __shared__ float a[D_];
    int row = blockIdx.x;
    for (int i = threadIdx.x; i < D_; i += 128)
        a[i] = h[(size_t)row * D_ + i];
    __syncthreads();

    int n = threadIdx.x;
    if (n < V_) {
        float acc = bias[n];
        #pragma unroll 4
        for (int kk = 0; kk < D_; kk++)
            acc = fmaf(a[kk], W[(size_t)kk * V_ + n], acc);
        out[(size_t)row * V_ + n] = acc;
    }
}

// ---------------------------------------------------------------------------
// Host launcher
// ---------------------------------------------------------------------------
static void launch_gemm(int M, int N, int K,
                        const __nv_bfloat16* Ah, const __nv_bfloat16* Al,
                        const __nv_bfloat16* Bh, const __nv_bfloat16* Bl,
                        const float* bias, float* C, int mode)
{
    dim3 grid(N / 128, M / 128);
    if (mode == 0)
        mma_gemm<false, false, false><<<grid, 256, GEMM_SMEM>>>(M, N, K, Ah, Al, Bh, Bl, bias, C);
    else if (mode == 1)
        mma_gemm<true, true, false><<<grid, 256, GEMM_SMEM>>>(M, N, K, Ah, Al, Bh, Bl, bias, C);
    else
        mma_gemm<true, false, true><<<grid, 256, GEMM_SMEM>>>(M, N, K, Ah, Al, Bh, Bl, bias, C);
}

extern "C" void kernel_launch(void* const* d_in, const int* in_sizes, int n_in,
                              void* d_out, int out_size)
{
    const int*   idx    = (const int*)  d_in[0];
    const float* tok    = (const float*)d_in[1];
    const float* pos    = (const float*)d_in[2];
    const float* ln1_s  = (const float*)d_in[3];
    const float* ln1_b  = (const float*)d_in[4];
    const float* wq     = (const float*)d_in[5];
    const float* wk     = (const float*)d_in[6];
    const float* wv     = (const float*)d_in[7];
    const float* wo     = (const float*)d_in[8];
    const float* bo     = (const float*)d_in[9];
    const float* ln2_s  = (const float*)d_in[10];
    const float* ln2_b  = (const float*)d_in[11];
    const float* w1     = (const float*)d_in[12];
    const float* b1     = (const float*)d_in[13];
    const float* w2     = (const float*)d_in[14];
    const float* b2     = (const float*)d_in[15];
    const float* lnf_s  = (const float*)d_in[16];
    const float* lnf_b  = (const float*)d_in[17];
    const float* head_w = (const float*)d_in[18];
    const float* head_b = (const float*)d_in[19];
    float* out = (float*)d_out;

    float *x, *h, *q, *k, *v, *ffn;
    __nv_bfloat16 *ah, *al, *wh, *wl;
    cudaGetSymbolAddress((void**)&x,   g_x);
    cudaGetSymbolAddress((void**)&h,   g_h);
    cudaGetSymbolAddress((void**)&q,   g_q);
    cudaGetSymbolAddress((void**)&k,   g_k);
    cudaGetSymbolAddress((void**)&v,   g_v);
    cudaGetSymbolAddress((void**)&ffn, g_ffn);
    cudaGetSymbolAddress((void**)&ah,  g_ah);
    cudaGetSymbolAddress((void**)&al,  g_al);
    cudaGetSymbolAddress((void**)&wh,  g_wh);
    cudaGetSymbolAddress((void**)&wl,  g_wl);

    cudaFuncSetAttribute(attn_kernel,
                         cudaFuncAttributeMaxDynamicSharedMemorySize,
                         2 * T_ * HD_ * (int)sizeof(float));
    cudaFuncSetAttribute(mma_gemm<false, false, false>,
                         cudaFuncAttributeMaxDynamicSharedMemorySize, GEMM_SMEM);
    cudaFuncSetAttribute(mma_gemm<true, true, false>,
                         cudaFuncAttributeMaxDynamicSharedMemorySize, GEMM_SMEM);
    cudaFuncSetAttribute(mma_gemm<true, false, true>,
                         cudaFuncAttributeMaxDynamicSharedMemorySize, GEMM_SMEM);

    // Weight transpose+split (all layers)
    {
        dim3 tb(32, 8);
        tsplit_kernel<<<dim3(D_ / 32,  D_ / 32,  L_), tb>>>(wq, wh + OFF_WQ, wl + OFF_WQ, D_,  D_);
        tsplit_kernel<<<dim3(D_ / 32,  D_ / 32,  L_), tb>>>(wk, wh + OFF_WK, wl + OFF_WK, D_,  D_);
        tsplit_kernel<<<dim3(D_ / 32,  D_ / 32,  L_), tb>>>(wv, wh + OFF_WV, wl + OFF_WV, D_,  D_);
        tsplit_kernel<<<dim3(D_ / 32,  D_ / 32,  L_), tb>>>(wo, wh + OFF_WO, wl + OFF_WO, D_,  D_);
        tsplit_kernel<<<dim3(FF_ / 32, D_ / 32,  L_), tb>>>(w1, wh + OFF_W1, wl + OFF_W1, D_,  FF_);
        tsplit_kernel<<<dim3(D_ / 32,  FF_ / 32, L_), tb>>>(w2, wh + OFF_W2, wl + OFF_W2, FF_, D_);
    }

    // Embedding
    embed_kernel<<<(NTOK * D_ + 255) / 256, 256>>>(idx, tok, pos, x);

    const int nD4  = NTOK * D_ / 4;
    const int nFF4 = NTOK * FF_ / 4;

    for (int l = 0; l < L_; l++) {
        const __nv_bfloat16* WqH = wh + OFF_WQ + (size_t)l * D_ * D_;
        const __nv_bfloat16* WqL = wl + OFF_WQ + (size_t)l * D_ * D_;
        const __nv_bfloat16* WkH = wh + OFF_WK + (size_t)l * D_ * D_;
        const __nv_bfloat16* WkL = wl + OFF_WK + (size_t)l * D_ * D_;
        const __nv_bfloat16* WvH = wh + OFF_WV + (size_t)l * D_ * D_;
        const __nv_bfloat16* WvL = wl + OFF_WV + (size_t)l * D_ * D_;
        const __nv_bfloat16* WoH = wh + OFF_WO + (size_t)l * D_ * D_;
        const __nv_bfloat16* WoL = wl + OFF_WO + (size_t)l * D_ * D_;
        const __nv_bfloat16* W1H = wh + OFF_W1 + (size_t)l * D_ * FF_;
        const __nv_bfloat16* W1L = wl + OFF_W1 + (size_t)l * D_ * FF_;
        const __nv_bfloat16* W2H = wh + OFF_W2 + (size_t)l * D_ * FF_;
        const __nv_bfloat16* W2L = wl + OFF_W2 + (size_t)l * D_ * FF_;
        const float* Bo = bo + (size_t)l * D_;
        const float* B1 = b1 + (size_t)l * FF_;
        const float* B2 = b2 + (size_t)l * D_;

        // ln1 -> h, split h
        layernorm_kernel<<<NTOK, 128>>>(x, ln1_s + (size_t)l * D_, ln1_b + (size_t)l * D_, h);
        split4_kernel<<<(nD4 + 255) / 256, 256>>>(h, ah, al, nD4);
        // q, k, v
        launch_gemm(NTOK, D_, D_, ah, al, WqH, WqL, nullptr, q, 0);
        launch_gemm(NTOK, D_, D_, ah, al, WkH, WkL, nullptr, k, 0);
        launch_gemm(NTOK, D_, D_, ah, al, WvH, WvL, nullptr, v, 0);
        // attention -> h
        attn_kernel<<<B_ * H_, 256, 2 * T_ * HD_ * (int)sizeof(float)>>>(q, k, v, h);
        // x += h @ Wo + Bo
        split4_kernel<<<(nD4 + 255) / 256, 256>>>(h, ah, al, nD4);
        launch_gemm(NTOK, D_, D_, ah, al, WoH, WoL, Bo, x, 2);
        // ln2 -> h, split
        layernorm_kernel<<<NTOK, 128>>>(x, ln2_s + (size_t)l * D_, ln2_b + (size_t)l * D_, h);
        split4_kernel<<<(nD4 + 255) / 256, 256>>>(h, ah, al, nD4);
        // ffn = relu(h @ W1 + B1)
        launch_gemm(NTOK, FF_, D_, ah, al, W1H, W1L, B1, ffn, 1);
        // x += ffn @ W2 + B2
        split4_kernel<<<(nFF4 + 255) / 256, 256>>>(ffn, ah, al, nFF4);
        launch_gemm(NTOK, D_, FF_, ah, al, W2H, W2L, B2, x, 2);
    }

    // Final layernorm + head
    layernorm_kernel<<<NTOK, 128>>>(x, lnf_s, lnf_b, h);
    head_kernel<<<NTOK, 128>>>(h, head_w, head_b, out);
}

// round 5
// speedup vs baseline: 1.9815x; 1.1162x over previous
#include <cuda_runtime.h>
#include <cuda_bf16.h>
#include <cstdint>

// Problem constants
#define B_    128
#define T_    256
#define D_    384
#define H_    6
#define HD_   64
#define L_    6
#define FF_   1536
#define V_    95
#define NTOK  (B_ * T_)   // 32768

extern __shared__ char dyn_smem[];

// ---------------------------------------------------------------------------
// Baseline-PTX helpers
// ---------------------------------------------------------------------------
__device__ __forceinline__ uint32_t smem_u32(const void* p) {
    uint32_t a;
    asm("{ .reg .u64 t; cvta.to.shared.u64 t, %1; cvt.u32.u64 %0, t; }"
        : "=r"(a) : "l"(p));
    return a;
}
__device__ __forceinline__ void cp16(uint32_t dst, const void* src) {
    asm volatile("cp.async.cg.shared.global [%0], [%1], 16;"
                 :: "r"(dst), "l"(src));
}
#define CP_COMMIT() asm volatile("cp.async.commit_group;" ::: "memory")
#define CP_WAIT0()  asm volatile("cp.async.wait_group 0;" ::: "memory")
#define CP_WAIT1()  asm volatile("cp.async.wait_group 1;" ::: "memory")

__device__ __forceinline__ void mma16816(float* c, const uint32_t* a,
                                         const uint32_t* b) {
    asm volatile(
        "mma.sync.aligned.m16n8k16.row.col.f32.bf16.bf16.f32 "
        "{%0,%1,%2,%3},{%4,%5,%6,%7},{%8,%9},{%0,%1,%2,%3};"
        : "+f"(c[0]), "+f"(c[1]), "+f"(c[2]), "+f"(c[3])
        : "r"(a[0]), "r"(a[1]), "r"(a[2]), "r"(a[3]),
          "r"(b[0]), "r"(b[1]));
}
__device__ __forceinline__ void ldsm4(uint32_t& r0, uint32_t& r1,
                                      uint32_t& r2, uint32_t& r3, uint32_t a) {
    asm volatile("ldmatrix.sync.aligned.m8n8.x4.shared.b16 {%0,%1,%2,%3}, [%4];"
                 : "=r"(r0), "=r"(r1), "=r"(r2), "=r"(r3) : "r"(a));
}

// ---------------------------------------------------------------------------
// Weight layout (per layer, packed): QKV[3D x D] | WO[D x D] | W1[FF x D] | W2[D x FF]
// All stored transposed: [N][K].
// ---------------------------------------------------------------------------
#define S_LAYER (4 * D_ * D_ + 2 * D_ * FF_)
#define OFF_QKV 0
#define OFF_WO  (3 * D_ * D_)
#define OFF_W1  (4 * D_ * D_)
#define OFF_W2  (4 * D_ * D_ + FF_ * D_)
#define WTOT    (L_ * S_LAYER)
#define HWPAD   (128 * D_)

__device__ float g_x[NTOK * D_];
__device__ float g_q[NTOK * D_];
__device__ float g_k[NTOK * D_];
__device__ float g_v[NTOK * D_];
__device__ __nv_bfloat16 g_ah[NTOK * D_],  g_al[NTOK * D_];
__device__ __nv_bfloat16 g_fh[NTOK * FF_], g_fl[NTOK * FF_];
__device__ __nv_bfloat16 g_wh[WTOT], g_wl[WTOT];
__device__ __nv_bfloat16 g_hwh[HWPAD], g_hwl[HWPAD];

// ---------------------------------------------------------------------------
// Embedding
// ---------------------------------------------------------------------------
__global__ void embed_kernel(const int* __restrict__ idx,
                             const float* __restrict__ tok,
                             const float* __restrict__ pos,
                             float* __restrict__ x)
{
    int i = blockIdx.x * blockDim.x + threadIdx.x;
    if (i >= NTOK * D_) return;
    int d   = i % D_;
    int row = i / D_;
    int t   = row % T_;
    int tk  = idx[row];
    x[i] = tok[tk * D_ + d] + pos[t * D_ + d];
}

// ---------------------------------------------------------------------------
// Fused LayerNorm + bf16 hi/lo split (one 128-thread block per token)
// ---------------------------------------------------------------------------
__global__ void __launch_bounds__(128)
lnsplit_kernel(const float* __restrict__ x,
               const float* __restrict__ gam,
               const float* __restrict__ beta,
               __nv_bfloat16* __restrict__ hi,
               __nv_bfloat16* __restrict__ lo)
{
    int row = blockIdx.x;
    int tid = threadIdx.x;
    const float* xr = x + (size_t)row * D_;

    float v0 = xr[tid];
    float v1 = xr[tid + 128];
    float v2 = xr[tid + 256];

    float s  = v0 + v1 + v2;
    float sq = v0 * v0 + v1 * v1 + v2 * v2;

    #pragma unroll
    for (int off = 16; off > 0; off >>= 1) {
        s  += __shfl_xor_sync(0xffffffffu, s,  off);
        sq += __shfl_xor_sync(0xffffffffu, sq, off);
    }
    __shared__ float ss[4], ssq[4];
    int w = tid >> 5;
    if ((tid & 31) == 0) { ss[w] = s; ssq[w] = sq; }
    __syncthreads();
    s  = ss[0]  + ss[1]  + ss[2]  + ss[3];
    sq = ssq[0] + ssq[1] + ssq[2] + ssq[3];

    const float invn = 1.0f / (float)D_;
    float mean = s * invn;
    float var  = sq * invn - mean * mean;
    float inv  = rsqrtf(var + 1e-5f);

    __nv_bfloat16* hp = hi + (size_t)row * D_;
    __nv_bfloat16* lp = lo + (size_t)row * D_;
    #pragma unroll
    for (int e = 0; e < 3; e++) {
        int   i2 = tid + e * 128;
        float vv = (e == 0) ? v0 : (e == 1) ? v1 : v2;
        float y  = (vv - mean) * inv * gam[i2] + beta[i2];
        __nv_bfloat16 h = __float2bfloat16(y);
        __nv_bfloat16 l = __float2bfloat16(y - __bfloat162float(h));
        hp[i2] = h;
        lp[i2] = l;
    }
}

// ---------------------------------------------------------------------------
// Transpose + split: W_in[z*in_z + k*Nd + n] -> out[z*out_z + n*Kd + k] (hi,lo)
// ---------------------------------------------------------------------------
__global__ void tsplit_kernel(const float* __restrict__ W,
                              __nv_bfloat16* __restrict__ oh,
                              __nv_bfloat16* __restrict__ ol,
                              int Kd, int Nd, long in_z, long out_z)
{
    __shared__ float t[32][33];
    int n0 = blockIdx.x * 32, k0 = blockIdx.y * 32;
    const float* Wz = W + (size_t)blockIdx.z * in_z;
    for (int r = threadIdx.y; r < 32; r += 8)
        t[r][threadIdx.x] = Wz[(size_t)(k0 + r) * Nd + n0 + threadIdx.x];
    __syncthreads();
    __nv_bfloat16* ohz = oh + (size_t)blockIdx.z * out_z;
    __nv_bfloat16* olz = ol + (size_t)blockIdx.z * out_z;
    for (int r = threadIdx.y; r < 32; r += 8) {
        float v = t[threadIdx.x][r];   // = W[k0+tx][n0+r]
        __nv_bfloat16 h = __float2bfloat16(v);
        __nv_bfloat16 l = __float2bfloat16(v - __bfloat162float(h));
        ohz[(size_t)(n0 + r) * Kd + k0 + threadIdx.x] = h;
        olz[(size_t)(n0 + r) * Kd + k0 + threadIdx.x] = l;
    }
}

// Head weight: W[D][V] -> padded transposed [128][D] hi/lo (rows >= V are zero)
__global__ void head_tsplit(const float* __restrict__ W,
                            __nv_bfloat16* __restrict__ oh,
                            __nv_bfloat16* __restrict__ ol)
{
    int i = blockIdx.x * blockDim.x + threadIdx.x;
    if (i >= 128 * D_) return;
    int n = i / D_, k = i % D_;
    float v = (n < V_) ? W[(size_t)k * V_ + n] : 0.0f;
    __nv_bfloat16 h = __float2bfloat16(v);
    __nv_bfloat16 l = __float2bfloat16(v - __bfloat162float(h));
    oh[i] = h;
    ol[i] = l;
}

// ---------------------------------------------------------------------------
// mma.sync GEMM with bf16x3 split, ldmatrix fragment loads.
// 128x128 CTA tile, BK=32, 8 warps (4x2), warp tile 32x64.
// smem: rows of 80B (64B data + 16B pad) -> conflict-free ldmatrix.
// ---------------------------------------------------------------------------
#define BKG      32
#define ROWB     80
#define TILE_B   (128 * ROWB)
#define STAGE_B  (4 * TILE_B)
#define GEMM_SMEM (2 * STAGE_B)   // 81920

template<bool BIAS, bool RELU, bool RESID, bool SPLITOUT>
__global__ void __launch_bounds__(256, 2)
mma_gemm(int M, int N, int K,
         const __nv_bfloat16* __restrict__ Ah,
         const __nv_bfloat16* __restrict__ Al,
         const __nv_bfloat16* __restrict__ Bh,   // [N,K]
         const __nv_bfloat16* __restrict__ Bl,   // [N,K]
         const float* __restrict__ bias,
         float* __restrict__ C0, float* __restrict__ C1, float* __restrict__ C2,
         int nsplit, int ldc, int nmax,
         __nv_bfloat16* __restrict__ oh, __nv_bfloat16* __restrict__ ol)
{
    char* smem = dyn_smem;
    const uint32_t sb = smem_u32(smem);

    const int tid  = threadIdx.x;
    const int wid  = tid >> 5;
    const int lane = tid & 31;
    const int wm   = wid & 3;
    const int wn   = wid >> 2;
    const int g    = lane >> 2;
    const int t    = lane & 3;

    const int n0 = blockIdx.x * 128;
    const int m0 = blockIdx.y * 128;

    const __nv_bfloat16* gsrc[4] = {
        Ah + (size_t)m0 * K, Al + (size_t)m0 * K,
        Bh + (size_t)n0 * K, Bl + (size_t)n0 * K };

    const int KT = K / BKG;

    auto load_stage = [&](int kt, int s) {
        const uint32_t sdst = sb + s * STAGE_B;
        const int kc = kt * BKG;
        #pragma unroll
        for (int tile = 0; tile < 4; tile++) {
            const __nv_bfloat16* gp = gsrc[tile];
            #pragma unroll
            for (int i = 0; i < 2; i++) {
                int idx = i * 256 + tid;
                int row = idx >> 2, ch = idx & 3;
                cp16(sdst + tile * TILE_B + row * ROWB + ch * 16,
                     gp + (size_t)row * K + kc + ch * 8);
            }
        }
    };

    float acc[2][8][4];
    #pragma unroll
    for (int i = 0; i < 2; i++)
        #pragma unroll
        for (int j = 0; j < 8; j++)
            #pragma unroll
            for (int c = 0; c < 4; c++) acc[i][j][c] = 0.0f;

    // per-lane ldmatrix offsets (row*80 + 16B-chunk)
    const uint32_t aOff = (uint32_t)((wm * 32 + (lane & 15)) * ROWB +
                                     ((lane >> 4) & 1) * 16);
    const uint32_t bOff = (uint32_t)((wn * 64 + (lane & 7) +
                                      ((lane >> 4) & 1) * 8) * ROWB +
                                     ((lane >> 3) & 1) * 16);

    load_stage(0, 0);
    CP_COMMIT();

    for (int kt = 0; kt < KT; kt++) {
        const int s = kt & 1;
        if (kt + 1 < KT) {
            load_stage(kt + 1, s ^ 1);
            CP_COMMIT();
            CP_WAIT1();
        } else {
            CP_WAIT0();
        }
        __syncthreads();

        const uint32_t base   = sb + s * STAGE_B;
        const uint32_t aBaseH = base + aOff;
        const uint32_t aBaseL = base + TILE_B + aOff;
        const uint32_t bBaseH = base + 2 * TILE_B + bOff;
        const uint32_t bBaseL = base + 3 * TILE_B + bOff;

        #pragma unroll
        for (int ks = 0; ks < 2; ks++) {
            uint32_t ah[2][4], al[2][4];
            #pragma unroll
            for (int i = 0; i < 2; i++) {
                ldsm4(ah[i][0], ah[i][1], ah[i][2], ah[i][3],
                      aBaseH + i * (16 * ROWB) + ks * 32);
                ldsm4(al[i][0], al[i][1], al[i][2], al[i][3],
                      aBaseL + i * (16 * ROWB) + ks * 32);
            }
            #pragma unroll
            for (int half = 0; half < 2; half++) {
                uint32_t bhr[8], blr[8];
                ldsm4(bhr[0], bhr[1], bhr[2], bhr[3],
                      bBaseH + (half * 32) * ROWB + ks * 32);
                ldsm4(bhr[4], bhr[5], bhr[6], bhr[7],
                      bBaseH + (half * 32 + 16) * ROWB + ks * 32);
                ldsm4(blr[0], blr[1], blr[2], blr[3],
                      bBaseL + (half * 32) * ROWB + ks * 32);
                ldsm4(blr[4], blr[5], blr[6], blr[7],
                      bBaseL + (half * 32 + 16) * ROWB + ks * 32);
                // product-outer ordering: long acc reuse distance
                #pragma unroll
                for (int i = 0; i < 2; i++)
                    #pragma unroll
                    for (int j4 = 0; j4 < 4; j4++)
                        mma16816(acc[i][half * 4 + j4], ah[i], &bhr[2 * j4]);
                #pragma unroll
                for (int i = 0; i < 2; i++)
                    #pragma unroll
                    for (int j4 = 0; j4 < 4; j4++)
                        mma16816(acc[i][half * 4 + j4], ah[i], &blr[2 * j4]);
                #pragma unroll
                for (int i = 0; i < 2; i++)
                    #pragma unroll
                    for (int j4 = 0; j4 < 4; j4++)
                        mma16816(acc[i][half * 4 + j4], al[i], &bhr[2 * j4]);
            }
        }
        __syncthreads();
    }

    // ---- epilogue ----
    const int which = n0 / nsplit;
    const int ncol0 = n0 - which * nsplit;
    float* Cb = (which == 0) ? C0 : (which == 1) ? C1 : C2;

    #pragma unroll
    for (int i = 0; i < 2; i++) {
        const int rm = m0 + wm * 32 + i * 16 + g;
        #pragma unroll
        for (int j = 0; j < 8; j++) {
            const int cnl = ncol0 + wn * 64 + j * 8 + 2 * t;  // local out col
            const int gn  = n0    + wn * 64 + j * 8 + 2 * t;  // global col
            float v00 = acc[i][j][0], v01 = acc[i][j][1];
            float v10 = acc[i][j][2], v11 = acc[i][j][3];
            if (BIAS) {
                float b0 = (gn     < nmax) ? bias[gn]     : 0.0f;
                float b1 = (gn + 1 < nmax) ? bias[gn + 1] : 0.0f;
                v00 += b0; v01 += b1; v10 += b0; v11 += b1;
            }
            if (RELU) {
                v00 = fmaxf(v00, 0.f); v01 = fmaxf(v01, 0.f);
                v10 = fmaxf(v10, 0.f); v11 = fmaxf(v11, 0.f);
            }
            if (SPLITOUT) {
                size_t p0 = (size_t)rm * ldc + cnl;
                size_t p1 = (size_t)(rm + 8) * ldc + cnl;
                __nv_bfloat16 h00 = __float2bfloat16(v00);
                __nv_bfloat16 h01 = __float2bfloat16(v01);
                __nv_bfloat16 h10 = __float2bfloat16(v10);
                __nv_bfloat16 h11 = __float2bfloat16(v11);
                __nv_bfloat16 l00 = __float2bfloat16(v00 - __bfloat162float(h00));
                __nv_bfloat16 l01 = __float2bfloat16(v01 - __bfloat162float(h01));
                __nv_bfloat16 l10 = __float2bfloat16(v10 - __bfloat162float(h10));
                __nv_bfloat16 l11 = __float2bfloat16(v11 - __bfloat162float(h11));
                *reinterpret_cast<__nv_bfloat162*>(oh + p0) = __nv_bfloat162{h00, h01};
                *reinterpret_cast<__nv_bfloat162*>(oh + p1) = __nv_bfloat162{h10, h11};
                *reinterpret_cast<__nv_bfloat162*>(ol + p0) = __nv_bfloat162{l00, l01};
                *reinterpret_cast<__nv_bfloat162*>(ol + p1) = __nv_bfloat162{l10, l11};
            } else if (nmax == N) {
                float* p0 = Cb + (size_t)rm * ldc + cnl;
                float* p1 = Cb + (size_t)(rm + 8) * ldc + cnl;
                float2 w0 = make_float2(v00, v01);
                float2 w1 = make_float2(v10, v11);
                if (RESID) {
                    float2 o0 = *reinterpret_cast<const float2*>(p0);
                    float2 o1 = *reinterpret_cast<const float2*>(p1);
                    w0.x += o0.x; w0.y += o0.y;
                    w1.x += o1.x; w1.y += o1.y;
                }
                *reinterpret_cast<float2*>(p0) = w0;
                *reinterpret_cast<float2*>(p1) = w1;
            } else {
                // guarded scalar path (head: ldc=95, nmax=95)
                if (gn < nmax) {
                    Cb[(size_t)rm * ldc + cnl]       = v00;
                    Cb[(size_t)(rm + 8) * ldc + cnl] = v10;
                }
                if (gn + 1 < nmax) {
                    Cb[(size_t)rm * ldc + cnl + 1]       = v01;
                    Cb[(size_t)(rm + 8) * ldc + cnl + 1] = v11;
                }
            }
        }
    }
}

// ---------------------------------------------------------------------------
// Causal attention; output written as split bf16 (hi/lo)
// ---------------------------------------------------------------------------
__global__ void __launch_bounds__(256)
attn_kernel(const float* __restrict__ q,
            const float* __restrict__ k,
            const float* __restrict__ v,
            __nv_bfloat16* __restrict__ oh,
            __nv_bfloat16* __restrict__ ol)
{
    float* smem = reinterpret_cast<float*>(dyn_smem);
    float* ks = smem;
    float* vs = smem + T_ * HD_;

    int bh = blockIdx.x;
    int b  = bh / H_;
    int h  = bh % H_;
    int tid = threadIdx.x;

    const size_t base = (size_t)(b * T_) * D_ + h * HD_;

    const float4* krow = reinterpret_cast<const float4*>(k + base + (size_t)tid * D_);
    const float4* vrow = reinterpret_cast<const float4*>(v + base + (size_t)tid * D_);
    float4* ksd = reinterpret_cast<float4*>(ks + tid * HD_);
    float4* vsd = reinterpret_cast<float4*>(vs + tid * HD_);
    #pragma unroll
    for (int d4 = 0; d4 < HD_ / 4; d4++) {
        ksd[d4] = krow[d4];
        vsd[d4] = vrow[d4];
    }
    __syncthreads();

    float qr[HD_];
    const float4* qrow = reinterpret_cast<const float4*>(q + base + (size_t)tid * D_);
    #pragma unroll
    for (int d4 = 0; d4 < HD_ / 4; d4++) {
        float4 tv = qrow[d4];
        qr[d4 * 4 + 0] = tv.x; qr[d4 * 4 + 1] = tv.y;
        qr[d4 * 4 + 2] = tv.z; qr[d4 * 4 + 3] = tv.w;
    }

    float m = -1e30f, l = 0.0f;
    float o[HD_];
    #pragma unroll
    for (int d = 0; d < HD_; d++) o[d] = 0.0f;

    const float scale = 0.125f;

    for (int j = 0; j <= tid; j++) {
        const float* kj = ks + j * HD_;
        float s = 0.0f;
        #pragma unroll
        for (int d = 0; d < HD_; d++) s = fmaf(qr[d], kj[d], s);
        s *= scale;

        if (s > m) {
            float corr = __expf(m - s);
            l *= corr;
            #pragma unroll
            for (int d = 0; d < HD_; d++) o[d] *= corr;
            m = s;
        }
        float p = __expf(s - m);
        l += p;
        const float* vj = vs + j * HD_;
        #pragma unroll
        for (int d = 0; d < HD_; d++) o[d] = fmaf(p, vj[d], o[d]);
    }

    float invl = 1.0f / l;
    __nv_bfloat16* hp = oh + base + (size_t)tid * D_;
    __nv_bfloat16* lp = ol + base + (size_t)tid * D_;
    #pragma unroll
    for (int d = 0; d < HD_; d++) {
        float val = o[d] * invl;
        __nv_bfloat16 hh = __float2bfloat16(val);
        __nv_bfloat16 ll = __float2bfloat16(val - __bfloat162float(hh));
        hp[d] = hh;
        lp[d] = ll;
    }
}

// ---------------------------------------------------------------------------
// Host launcher
// ---------------------------------------------------------------------------
extern "C" void kernel_launch(void* const* d_in, const int* in_sizes, int n_in,
                              void* d_out, int out_size)
{
    const int*   idx    = (const int*)  d_in[0];
    const float* tok    = (const float*)d_in[1];
    const float* pos    = (const float*)d_in[2];
    const float* ln1_s  = (const float*)d_in[3];
    const float* ln1_b  = (const float*)d_in[4];
    const float* wq     = (const float*)d_in[5];
    const float* wk     = (const float*)d_in[6];
    const float* wv     = (const float*)d_in[7];
    const float* wo     = (const float*)d_in[8];
    const float* bo     = (const float*)d_in[9];
    const float* ln2_s  = (const float*)d_in[10];
    const float* ln2_b  = (const float*)d_in[11];
    const float* w1     = (const float*)d_in[12];
    const float* b1     = (const float*)d_in[13];
    const float* w2     = (const float*)d_in[14];
    const float* b2     = (const float*)d_in[15];
    const float* lnf_s  = (const float*)d_in[16];
    const float* lnf_b  = (const float*)d_in[17];
    const float* head_w = (const float*)d_in[18];
    const float* head_b = (const float*)d_in[19];
    float* out = (float*)d_out;

    float *x, *q, *k, *v;
    __nv_bfloat16 *ah, *al, *fh, *fl, *wh, *wl, *hwh, *hwl;
    cudaGetSymbolAddress((void**)&x,   g_x);
    cudaGetSymbolAddress((void**)&q,   g_q);
    cudaGetSymbolAddress((void**)&k,   g_k);
    cudaGetSymbolAddress((void**)&v,   g_v);
    cudaGetSymbolAddress((void**)&ah,  g_ah);
    cudaGetSymbolAddress((void**)&al,  g_al);
    cudaGetSymbolAddress((void**)&fh,  g_fh);
    cudaGetSymbolAddress((void**)&fl,  g_fl);
    cudaGetSymbolAddress((void**)&wh,  g_wh);
    cudaGetSymbolAddress((void**)&wl,  g_wl);
    cudaGetSymbolAddress((void**)&hwh, g_hwh);
    cudaGetSymbolAddress((void**)&hwl, g_hwl);

    cudaFuncSetAttribute(attn_kernel,
                         cudaFuncAttributeMaxDynamicSharedMemorySize,
                         2 * T_ * HD_ * (int)sizeof(float));
    cudaFuncSetAttribute((const void*)mma_gemm<false, false, false, false>,
                         cudaFuncAttributeMaxDynamicSharedMemorySize, GEMM_SMEM);
    cudaFuncSetAttribute((const void*)mma_gemm<true, false, true, false>,
                         cudaFuncAttributeMaxDynamicSharedMemorySize, GEMM_SMEM);
    cudaFuncSetAttribute((const void*)mma_gemm<true, true, false, true>,
                         cudaFuncAttributeMaxDynamicSharedMemorySize, GEMM_SMEM);
    cudaFuncSetAttribute((const void*)mma_gemm<true, false, false, false>,
                         cudaFuncAttributeMaxDynamicSharedMemorySize, GEMM_SMEM);

    // ---- weight transpose + split (packed per-layer layout) ----
    {
        dim3 tb(32, 8);
        long DD = (long)D_ * D_, DFF = (long)D_ * FF_;
        tsplit_kernel<<<dim3(D_/32, D_/32, L_), tb>>>(wq, wh + OFF_QKV,          wl + OFF_QKV,          D_,  D_,  DD,  S_LAYER);
        tsplit_kernel<<<dim3(D_/32, D_/32, L_), tb>>>(wk, wh + OFF_QKV + D_*D_,  wl + OFF_QKV + D_*D_,  D_,  D_,  DD,  S_LAYER);
        tsplit_kernel<<<dim3(D_/32, D_/32, L_), tb>>>(wv, wh + OFF_QKV + 2*D_*D_,wl + OFF_QKV + 2*D_*D_,D_,  D_,  DD,  S_LAYER);
        tsplit_kernel<<<dim3(D_/32, D_/32, L_), tb>>>(wo, wh + OFF_WO,           wl + OFF_WO,           D_,  D_,  DD,  S_LAYER);
        tsplit_kernel<<<dim3(FF_/32, D_/32, L_), tb>>>(w1, wh + OFF_W1,          wl + OFF_W1,           D_,  FF_, DFF, S_LAYER);
        tsplit_kernel<<<dim3(D_/32, FF_/32, L_), tb>>>(w2, wh + OFF_W2,          wl + OFF_W2,           FF_, D_,  DFF, S_LAYER);
        head_tsplit<<<(128 * D_ + 255) / 256, 256>>>(head_w, hwh, hwl);
    }

    // ---- embedding ----
    embed_kernel<<<(NTOK * D_ + 255) / 256, 256>>>(idx, tok, pos, x);

    for (int l = 0; l < L_; l++) {
        const __nv_bfloat16* WH = wh + (size_t)l * S_LAYER;
        const __nv_bfloat16* WL = wl + (size_t)l * S_LAYER;
        const float* Bo = bo + (size_t)l * D_;
        const float* B1 = b1 + (size_t)l * FF_;
        const float* B2 = b2 + (size_t)l * D_;

        // ln1 + split
        lnsplit_kernel<<<NTOK, 128>>>(x, ln1_s + (size_t)l * D_, ln1_b + (size_t)l * D_, ah, al);
        // fused QKV (N=1152)
        mma_gemm<false, false, false, false><<<dim3(9, 256), 256, GEMM_SMEM>>>(
            NTOK, 3 * D_, D_, ah, al, WH + OFF_QKV, WL + OFF_QKV, nullptr,
            q, k, v, D_, D_, 3 * D_, nullptr, nullptr);
        // attention -> ah/al
        attn_kernel<<<B_ * H_, 256, 2 * T_ * HD_ * (int)sizeof(float)>>>(q, k, v, ah, al);
        // x += attn @ Wo + Bo
        mma_gemm<true, false, true, false><<<dim3(3, 256), 256, GEMM_SMEM>>>(
            NTOK, D_, D_, ah, al, WH + OFF_WO, WL + OFF_WO, Bo,
            x, x, x, D_, D_, D_, nullptr, nullptr);
        // ln2 + split
        lnsplit_kernel<<<NTOK, 128>>>(x, ln2_s + (size_t)l * D_, ln2_b + (size_t)l * D_, ah, al);
        // ffn = relu(h @ W1 + B1) -> split bf16 directly
        mma_gemm<true, true, false, true><<<dim3(12, 256), 256, GEMM_SMEM>>>(
            NTOK, FF_, D_, ah, al, WH + OFF_W1, WL + OFF_W1, B1,
            x, x, x, FF_, FF_, FF_, fh, fl);
        // x += ffn @ W2 + B2
        mma_gemm<true, false, true, false><<<dim3(3, 256), 256, GEMM_SMEM>>>(
            NTOK, D_, FF_, fh, fl, WH + OFF_W2, WL + OFF_W2, B2,
            x, x, x, D_, D_, D_, nullptr, nullptr);
    }

    // final layernorm + split, then head GEMM (N padded to 128, guarded to 95)
    lnsplit_kernel<<<NTOK, 128>>>(x, lnf_s, lnf_b, ah, al);
    mma_gemm<true, false, false, false><<<dim3(1, 256), 256, GEMM_SMEM>>>(
        NTOK, 128, D_, ah, al, hwh, hwl, head_b,
        out, out, out, 128, V_, V_, nullptr, nullptr);
}